// round 8
// baseline (speedup 1.0000x reference)
#include <cuda_runtime.h>

#define KK      32
#define HH      4096
#define OUTN    4065
#define EPSV    1e-8f

#define THREADS 256
#define NWARP   8
#define WPC     64           // output cols per warp
#define WC      512          // output cols per block
#define NSTRIP  8
#define ROWTILES 37
#define ROUT    110
#define DEPTH   4            // prefetch depth (rows)

// smem floats: img 1024 + hist 8 warps * 32 slots * 64 cols = 16384
#define SMEM_FLOATS (1024 + NWARP * KK * WPC)

template<int B>
__device__ __forceinline__ void row_step(
    int ir, int r0, int lane, int rows_out,
    int col0, int col1, int col2, int base,
    const float* __restrict__ som, const float* __restrict__ var,
    const float* __restrict__ s_img, float* __restrict__ hp,
    float* __restrict__ out,
    float (&sb)[DEPTH][3], float (&vb)[DEPTH][3],
    float& acc0, float& acc1)
{
    const unsigned FULL = 0xffffffffu;
    const int gr = r0 + ir;

    // variance-weighted squared distances for the 3 input cols this lane owns
    const float iv = s_img[((gr & 31) << 5) + lane];
    const float d0 = iv - sb[B][0];
    const float d1 = iv - sb[B][1];
    const float d2 = iv - sb[B][2];
    const float e0 = __fdividef(d0 * d0, vb[B][0] + EPSV);
    const float e1 = __fdividef(d1 * d1, vb[B][1] + EPSV);
    const float e2 = __fdividef(d2 * d2, vb[B][2] + EPSV);

    // refill buffer B with row gr+DEPTH immediately (clamped row => valid address)
    {
        const int pr = min(gr + DEPTH, HH - 1);
        const float* sr = som + (size_t)pr * HH;
        const float* vr = var + (size_t)pr * HH;
        sb[B][0] = __ldg(sr + col0); sb[B][1] = __ldg(sr + col1); sb[B][2] = __ldg(sr + col2);
        vb[B][0] = __ldg(vr + col0); vb[B][1] = __ldg(vr + col1); vb[B][2] = __ldg(vr + col2);
    }

    // three interleaved warp inclusive scans
    float S0 = e0, S1 = e1, S2 = e2;
#pragma unroll
    for (int o = 1; o < 32; o <<= 1) {
        float a0 = __shfl_up_sync(FULL, S0, o);
        float a1 = __shfl_up_sync(FULL, S1, o);
        float a2 = __shfl_up_sync(FULL, S2, o);
        if (lane >= o) { S0 += a0; S1 += a1; S2 += a2; }
    }
    // carry segment totals: S_j becomes inclusive prefix at input col 32j+lane
    const float T0 = __shfl_sync(FULL, S0, 31);
    const float T1 = __shfl_sync(FULL, S1, 31);
    S1 += T0;
    S2 += T0 + T1;
    const float D1 = S1 - S0;
    const float D2 = S2 - S1;

    // horizontal 32-wide window sums via prefix differences
    const float u1 = __shfl_up_sync(FULL, D1, 1);
    const float u2 = __shfl_up_sync(FULL, D2, 1);
    const float b0 = __shfl_sync(FULL, S0, 31);   // window @ warp col 0
    const float b1 = __shfl_sync(FULL, D1, 31);   // window @ warp col 32
    const float h0 = (lane == 0) ? b0 : u1;
    const float h1 = (lane == 0) ? b1 : u2;

    // vertical sliding window via warp-private 32-row smem ring (no sync needed)
    float* hs = hp + ((ir & 31) << 6);
    float o0 = 0.f, o1 = 0.f;
    if (ir >= KK) { o0 = hs[0]; o1 = hs[32]; }
    acc0 += h0 - o0;
    acc1 += h1 - o1;
    hs[0] = h0;
    hs[32] = h1;

    // emit once window full; never write rows owned by the next row-tile
    if (ir >= KK - 1 && ir < rows_out + KK - 1) {
        const int orow = gr - (KK - 1);
        if (orow < OUTN) {
            float* op = out + (size_t)orow * OUTN + base;
            op[0] = acc0;                          // base <= 4063 < OUTN always
            if (base + 32 < OUTN) op[32] = acc1;
        }
    }
}

__global__ __launch_bounds__(THREADS, 2)
void som_boxdist_kernel(const float* __restrict__ img,
                        const float* __restrict__ som,
                        const float* __restrict__ var,
                        float* __restrict__ out)
{
    extern __shared__ __align__(16) float smem[];
    float* s_img = smem;                 // 1024 floats
    float* hist  = smem + 1024;          // [warp][slot][2][32]

    const int t    = threadIdx.x;
    const int lane = t & 31;
    const int w    = t >> 5;
    const int c0   = blockIdx.x * WC;
    const int r0   = blockIdx.y * ROUT;
    const int rows_out = min(ROUT, OUTN - r0);
    const int rows_in  = rows_out + KK - 1;

    const int base = c0 + w * WPC + lane;        // lane's first input/output col
    const int col0 = min(base,      HH - 1);     // clamped (right edge)
    const int col1 = min(base + 32, HH - 1);
    const int col2 = min(base + 64, HH - 1);

    for (int i = t; i < KK * KK; i += THREADS) s_img[i] = img[i];

    // depth-4 register prefetch ring
    float sb[DEPTH][3], vb[DEPTH][3];
#pragma unroll
    for (int d = 0; d < DEPTH; ++d) {
        const int pr = min(r0 + d, HH - 1);
        const float* sr = som + (size_t)pr * HH;
        const float* vr = var + (size_t)pr * HH;
        sb[d][0] = __ldg(sr + col0); sb[d][1] = __ldg(sr + col1); sb[d][2] = __ldg(sr + col2);
        vb[d][0] = __ldg(vr + col0); vb[d][1] = __ldg(vr + col1); vb[d][2] = __ldg(vr + col2);
    }

    __syncthreads();    // s_img ready (the ONLY barrier)

    float acc0 = 0.f, acc1 = 0.f;
    float* hp = hist + w * (KK * WPC) + lane;    // + slot*64 (+32 for 2nd col)

    const int nloop = ((rows_in + DEPTH - 1) / DEPTH) * DEPTH;

    for (int ir = 0; ir < nloop; ir += DEPTH) {
        row_step<0>(ir + 0, r0, lane, rows_out, col0, col1, col2, base,
                    som, var, s_img, hp, out, sb, vb, acc0, acc1);
        row_step<1>(ir + 1, r0, lane, rows_out, col0, col1, col2, base,
                    som, var, s_img, hp, out, sb, vb, acc0, acc1);
        row_step<2>(ir + 2, r0, lane, rows_out, col0, col1, col2, base,
                    som, var, s_img, hp, out, sb, vb, acc0, acc1);
        row_step<3>(ir + 3, r0, lane, rows_out, col0, col1, col2, base,
                    som, var, s_img, hp, out, sb, vb, acc0, acc1);
    }
}

extern "C" void kernel_launch(void* const* d_in, const int* in_sizes, int n_in,
                              void* d_out, int out_size)
{
    (void)in_sizes; (void)n_in; (void)out_size;
    const float* img = (const float*)d_in[0];
    const float* som = (const float*)d_in[1];
    const float* var = (const float*)d_in[2];
    float* out = (float*)d_out;

    const size_t shmem = (size_t)SMEM_FLOATS * sizeof(float);   // 69,632 B
    cudaFuncSetAttribute(som_boxdist_kernel,
                         cudaFuncAttributeMaxDynamicSharedMemorySize, (int)shmem);

    dim3 grid(NSTRIP, ROWTILES);                 // 8 x 37 = 296 blocks, 2/SM
    som_boxdist_kernel<<<grid, THREADS, shmem>>>(img, som, var, out);
}

// round 10
// speedup vs baseline: 1.1543x; 1.1543x over previous
#include <cuda_runtime.h>

#define KK      32
#define HH      4096
#define OUTN    4065
#define EPSV    1e-8f

#define THREADS 512
#define NWARP   16
#define WPC     64           // output cols per warp
#define WC      1024         // output cols per block
#define NSTRIP  4
#define ROWTILES 37
#define ROUT    110
#define DEPTH   4            // prefetch depth (rows), pairs of 2

// smem floats: img 1024 + hist 16 warps * 32 slots * 64 cols = 32768
#define SMEM_FLOATS (1024 + NWARP * KK * WPC)

// Process rows ir and ir+1 together: 8 independent shuffle chains in flight.
template<int PB>    // pair-buffer: uses sb[2*PB], sb[2*PB+1]
__device__ __forceinline__ void row_pair(
    int ir, int r0, int lane, int rows_in,
    int col0, int col1, int col2, int base,
    const float* __restrict__ som, const float* __restrict__ var,
    const float* __restrict__ s_img, float* __restrict__ hp,
    float* __restrict__ out,
    float (&sb)[DEPTH][3], float (&vb)[DEPTH][3],
    float& acc0, float& acc1)
{
    const unsigned FULL = 0xffffffffu;
    const int gra = r0 + ir;
    const int grb = gra + 1;
    const int Ba = 2 * PB, Bb = 2 * PB + 1;

    // --- distances for both rows (independent) ---
    const float iva = s_img[((gra & 31) << 5) + lane];
    const float ivb = s_img[((grb & 31) << 5) + lane];

    float da0 = iva - sb[Ba][0], da1 = iva - sb[Ba][1], da2 = iva - sb[Ba][2];
    float db0 = ivb - sb[Bb][0], db1 = ivb - sb[Bb][1], db2 = ivb - sb[Bb][2];
    const float ea0 = __fdividef(da0 * da0, vb[Ba][0] + EPSV);
    const float ea1 = __fdividef(da1 * da1, vb[Ba][1] + EPSV);
    const float ea2 = __fdividef(da2 * da2, vb[Ba][2] + EPSV);
    const float eb0 = __fdividef(db0 * db0, vb[Bb][0] + EPSV);
    const float eb1 = __fdividef(db1 * db1, vb[Bb][1] + EPSV);
    const float eb2 = __fdividef(db2 * db2, vb[Bb][2] + EPSV);

    // --- refill both buffers with rows gr+DEPTH (clamped => always valid) ---
    {
        const int pa = min(gra + DEPTH, HH - 1);
        const int pb = min(grb + DEPTH, HH - 1);
        const float* sra = som + (size_t)pa * HH;
        const float* vra = var + (size_t)pa * HH;
        const float* srb = som + (size_t)pb * HH;
        const float* vrb = var + (size_t)pb * HH;
        sb[Ba][0] = __ldg(sra + col0); sb[Ba][1] = __ldg(sra + col1); sb[Ba][2] = __ldg(sra + col2);
        sb[Bb][0] = __ldg(srb + col0); sb[Bb][1] = __ldg(srb + col1); sb[Bb][2] = __ldg(srb + col2);
        vb[Ba][0] = __ldg(vra + col0); vb[Ba][1] = __ldg(vra + col1); vb[Ba][2] = __ldg(vra + col2);
        vb[Bb][0] = __ldg(vrb + col0); vb[Bb][1] = __ldg(vrb + col1); vb[Bb][2] = __ldg(vrb + col2);
    }

    // --- 4 interleaved xor-butterfly totals ---
    float Ta0 = ea0, Ta1 = ea1, Tb0 = eb0, Tb1 = eb1;
#pragma unroll
    for (int o = 16; o > 0; o >>= 1) {
        Ta0 += __shfl_xor_sync(FULL, Ta0, o);
        Ta1 += __shfl_xor_sync(FULL, Ta1, o);
        Tb0 += __shfl_xor_sync(FULL, Tb0, o);
        Tb1 += __shfl_xor_sync(FULL, Tb1, o);
    }

    // --- 4 interleaved inclusive scans of the sliding differences ---
    float Aa = ea1 - ea0, Ba_ = ea2 - ea1;
    float Ab = eb1 - eb0, Bb_ = eb2 - eb1;
#pragma unroll
    for (int o = 1; o < 32; o <<= 1) {
        float x0 = __shfl_up_sync(FULL, Aa,  o);
        float x1 = __shfl_up_sync(FULL, Ba_, o);
        float x2 = __shfl_up_sync(FULL, Ab,  o);
        float x3 = __shfl_up_sync(FULL, Bb_, o);
        if (lane >= o) { Aa += x0; Ba_ += x1; Ab += x2; Bb_ += x3; }
    }
    // exclusive shift
    float eAa = __shfl_up_sync(FULL, Aa,  1);
    float eBa = __shfl_up_sync(FULL, Ba_, 1);
    float eAb = __shfl_up_sync(FULL, Ab,  1);
    float eBb = __shfl_up_sync(FULL, Bb_, 1);
    if (lane == 0) { eAa = 0.f; eBa = 0.f; eAb = 0.f; eBb = 0.f; }

    const float ha0 = Ta0 + eAa;     // row a, window @ col base
    const float ha1 = Ta1 + eBa;     // row a, window @ col base+32
    const float hb0 = Tb0 + eAb;     // row b
    const float hb1 = Tb1 + eBb;

    // --- vertical sliding ring + emit, row a then row b (short serial part) ---
    {
        float* hs = hp + ((ir & 31) << 6);
        float o0 = 0.f, o1 = 0.f;
        if (ir >= KK) { o0 = hs[0]; o1 = hs[32]; }
        acc0 += ha0 - o0;
        acc1 += ha1 - o1;
        hs[0] = ha0; hs[32] = ha1;
        if (ir >= KK - 1 && ir < rows_in) {
            const int orow = gra - (KK - 1);
            float* op = out + (size_t)orow * OUTN + base;
            op[0] = acc0;                          // base <= 4063 < OUTN
            if (base + 32 < OUTN) op[32] = acc1;
        }
    }
    {
        const int jr = ir + 1;
        float* hs = hp + ((jr & 31) << 6);
        float o0 = 0.f, o1 = 0.f;
        if (jr >= KK) { o0 = hs[0]; o1 = hs[32]; }
        acc0 += hb0 - o0;
        acc1 += hb1 - o1;
        hs[0] = hb0; hs[32] = hb1;
        if (jr >= KK - 1 && jr < rows_in) {
            const int orow = grb - (KK - 1);
            float* op = out + (size_t)orow * OUTN + base;
            op[0] = acc0;
            if (base + 32 < OUTN) op[32] = acc1;
        }
    }
}

__global__ __launch_bounds__(THREADS, 1)
void som_boxdist_kernel(const float* __restrict__ img,
                        const float* __restrict__ som,
                        const float* __restrict__ var,
                        float* __restrict__ out)
{
    extern __shared__ __align__(16) float smem[];
    float* s_img = smem;                 // 1024 floats
    float* hist  = smem + 1024;          // [warp][slot][2][32]

    const int t    = threadIdx.x;
    const int lane = t & 31;
    const int w    = t >> 5;
    const int c0   = blockIdx.x * WC;
    const int r0   = blockIdx.y * ROUT;
    const int rows_out = min(ROUT, OUTN - r0);
    const int rows_in  = rows_out + KK - 1;

    const int base = c0 + w * WPC + lane;        // lane's first input/output col
    const int col0 = min(base,      HH - 1);     // clamped (right edge)
    const int col1 = min(base + 32, HH - 1);
    const int col2 = min(base + 64, HH - 1);

    for (int i = t; i < KK * KK; i += THREADS) s_img[i] = img[i];

    // depth-4 register prefetch ring
    float sb[DEPTH][3], vb[DEPTH][3];
#pragma unroll
    for (int d = 0; d < DEPTH; ++d) {
        const int pr = min(r0 + d, HH - 1);
        const float* sr = som + (size_t)pr * HH;
        const float* vr = var + (size_t)pr * HH;
        sb[d][0] = __ldg(sr + col0); sb[d][1] = __ldg(sr + col1); sb[d][2] = __ldg(sr + col2);
        vb[d][0] = __ldg(vr + col0); vb[d][1] = __ldg(vr + col1); vb[d][2] = __ldg(vr + col2);
    }

    __syncthreads();    // s_img ready (the ONLY barrier)

    float acc0 = 0.f, acc1 = 0.f;
    float* hp = hist + w * (KK * WPC) + lane;    // + slot*64 (+32 for 2nd col)

    const int nloop = ((rows_in + DEPTH - 1) / DEPTH) * DEPTH;   // multiple of 4

    for (int ir = 0; ir < nloop; ir += DEPTH) {
        row_pair<0>(ir,     r0, lane, rows_in, col0, col1, col2, base,
                    som, var, s_img, hp, out, sb, vb, acc0, acc1);
        row_pair<1>(ir + 2, r0, lane, rows_in, col0, col1, col2, base,
                    som, var, s_img, hp, out, sb, vb, acc0, acc1);
    }
}

extern "C" void kernel_launch(void* const* d_in, const int* in_sizes, int n_in,
                              void* d_out, int out_size)
{
    (void)in_sizes; (void)n_in; (void)out_size;
    const float* img = (const float*)d_in[0];
    const float* som = (const float*)d_in[1];
    const float* var = (const float*)d_in[2];
    float* out = (float*)d_out;

    const size_t shmem = (size_t)SMEM_FLOATS * sizeof(float);   // 135,168 B
    cudaFuncSetAttribute(som_boxdist_kernel,
                         cudaFuncAttributeMaxDynamicSharedMemorySize, (int)shmem);

    dim3 grid(NSTRIP, ROWTILES);                 // 148 blocks = 1/SM, 16 warps
    som_boxdist_kernel<<<grid, THREADS, shmem>>>(img, som, var, out);
}

// round 11
// speedup vs baseline: 1.2282x; 1.0640x over previous
#include <cuda_runtime.h>
#include <cuda_fp16.h>

#define KK      32
#define HH      4096
#define OUTN    4065
#define EPSV    1e-8f

#define THREADS 512
#define NWARP   16
#define WPC     64           // output cols per warp
#define WC      1024         // output cols per block
#define NSTRIP  4
#define ROWTILES 37
#define ROUT    110
#define DEPTH   4            // prefetch depth (rows), pairs of 2

// smem: img 1024 floats + hist 16 warps * 32 slots * 32 lanes * half2
#define SMEM_BYTES (1024 * 4 + NWARP * KK * 32 * 4)

// Process rows ir and ir+1 together; difference scans packed into half2.
template<int PB>    // pair-buffer: uses sb[2*PB], sb[2*PB+1]
__device__ __forceinline__ void row_pair(
    int ir, int r0, int lane, int rows_in,
    int col0, int col1, int col2, int base,
    const float* __restrict__ som, const float* __restrict__ var,
    const float* __restrict__ s_img, __half2* __restrict__ hp,
    float* __restrict__ out,
    float (&sb)[DEPTH][3], float (&vb)[DEPTH][3],
    float& acc0, float& acc1)
{
    const unsigned FULL = 0xffffffffu;
    const int gra = r0 + ir;
    const int grb = gra + 1;
    const int Ba = 2 * PB, Bb = 2 * PB + 1;

    // --- distances for both rows (fp32) ---
    const float iva = s_img[((gra & 31) << 5) + lane];
    const float ivb = s_img[((grb & 31) << 5) + lane];

    float da0 = iva - sb[Ba][0], da1 = iva - sb[Ba][1], da2 = iva - sb[Ba][2];
    float db0 = ivb - sb[Bb][0], db1 = ivb - sb[Bb][1], db2 = ivb - sb[Bb][2];
    const float ea0 = __fdividef(da0 * da0, vb[Ba][0] + EPSV);
    const float ea1 = __fdividef(da1 * da1, vb[Ba][1] + EPSV);
    const float ea2 = __fdividef(da2 * da2, vb[Ba][2] + EPSV);
    const float eb0 = __fdividef(db0 * db0, vb[Bb][0] + EPSV);
    const float eb1 = __fdividef(db1 * db1, vb[Bb][1] + EPSV);
    const float eb2 = __fdividef(db2 * db2, vb[Bb][2] + EPSV);

    // --- refill both buffers with rows gr+DEPTH (clamped => valid address) ---
    {
        const int pa = min(gra + DEPTH, HH - 1);
        const int pb = min(grb + DEPTH, HH - 1);
        const float* sra = som + (size_t)pa * HH;
        const float* vra = var + (size_t)pa * HH;
        const float* srb = som + (size_t)pb * HH;
        const float* vrb = var + (size_t)pb * HH;
        sb[Ba][0] = __ldg(sra + col0); sb[Ba][1] = __ldg(sra + col1); sb[Ba][2] = __ldg(sra + col2);
        sb[Bb][0] = __ldg(srb + col0); sb[Bb][1] = __ldg(srb + col1); sb[Bb][2] = __ldg(srb + col2);
        vb[Ba][0] = __ldg(vra + col0); vb[Ba][1] = __ldg(vra + col1); vb[Ba][2] = __ldg(vra + col2);
        vb[Bb][0] = __ldg(vrb + col0); vb[Bb][1] = __ldg(vrb + col1); vb[Bb][2] = __ldg(vrb + col2);
    }

    // --- 4 interleaved fp32 xor-butterfly totals (keep bulk magnitude in fp32) ---
    float Ta0 = ea0, Ta1 = ea1, Tb0 = eb0, Tb1 = eb1;
#pragma unroll
    for (int o = 16; o > 0; o >>= 1) {
        Ta0 += __shfl_xor_sync(FULL, Ta0, o);
        Ta1 += __shfl_xor_sync(FULL, Ta1, o);
        Tb0 += __shfl_xor_sync(FULL, Tb0, o);
        Tb1 += __shfl_xor_sync(FULL, Tb1, o);
    }

    // --- 2 half2-packed inclusive scans of the (near-zero-mean) differences ---
    // A: (ea1-ea0 | eb1-eb0), B: (ea2-ea1 | eb2-eb1)
    __half2 A = __floats2half2_rn(ea1 - ea0, eb1 - eb0);
    __half2 B = __floats2half2_rn(ea2 - ea1, eb2 - eb1);
#pragma unroll
    for (int o = 1; o < 32; o <<= 1) {
        __half2 xa = __shfl_up_sync(FULL, A, o);
        __half2 xb = __shfl_up_sync(FULL, B, o);
        if (lane >= o) { A = __hadd2(A, xa); B = __hadd2(B, xb); }
    }
    // exclusive shift (lane 0 -> zero in both halves)
    __half2 eAp = __shfl_up_sync(FULL, A, 1);
    __half2 eBp = __shfl_up_sync(FULL, B, 1);
    if (lane == 0) {
        eAp = __floats2half2_rn(0.f, 0.f);
        eBp = __floats2half2_rn(0.f, 0.f);
    }
    const float2 fA = __half22float2(eAp);   // (.x = row a, .y = row b)
    const float2 fB = __half22float2(eBp);

    const float ha0 = Ta0 + fA.x;     // row a, window @ col base
    const float ha1 = Ta1 + fB.x;     // row a, window @ col base+32
    const float hb0 = Tb0 + fA.y;     // row b
    const float hb1 = Tb1 + fB.y;

    // --- vertical sliding half2 ring + emit (round through fp16 first so the
    //     add and the later subtract cancel exactly) ---
    {
        const __half2 hh = __floats2half2_rn(ha0, ha1);
        const float2 hr = __half22float2(hh);
        __half2* hs = hp + ((ir & 31) << 5);
        float o0 = 0.f, o1 = 0.f;
        if (ir >= KK) { const float2 old = __half22float2(*hs); o0 = old.x; o1 = old.y; }
        acc0 += hr.x - o0;
        acc1 += hr.y - o1;
        *hs = hh;
        if (ir >= KK - 1 && ir < rows_in) {
            const int orow = gra - (KK - 1);
            float* op = out + (size_t)orow * OUTN + base;
            op[0] = acc0;                          // base <= 4063 < OUTN
            if (base + 32 < OUTN) op[32] = acc1;
        }
    }
    {
        const int jr = ir + 1;
        const __half2 hh = __floats2half2_rn(hb0, hb1);
        const float2 hr = __half22float2(hh);
        __half2* hs = hp + ((jr & 31) << 5);
        float o0 = 0.f, o1 = 0.f;
        if (jr >= KK) { const float2 old = __half22float2(*hs); o0 = old.x; o1 = old.y; }
        acc0 += hr.x - o0;
        acc1 += hr.y - o1;
        *hs = hh;
        if (jr >= KK - 1 && jr < rows_in) {
            const int orow = grb - (KK - 1);
            float* op = out + (size_t)orow * OUTN + base;
            op[0] = acc0;
            if (base + 32 < OUTN) op[32] = acc1;
        }
    }
}

__global__ __launch_bounds__(THREADS, 1)
void som_boxdist_kernel(const float* __restrict__ img,
                        const float* __restrict__ som,
                        const float* __restrict__ var,
                        float* __restrict__ out)
{
    extern __shared__ __align__(16) float smem[];
    float*   s_img = smem;                       // 1024 floats
    __half2* hist  = (__half2*)(smem + 1024);    // [warp][slot][lane]

    const int t    = threadIdx.x;
    const int lane = t & 31;
    const int w    = t >> 5;
    const int c0   = blockIdx.x * WC;
    const int r0   = blockIdx.y * ROUT;
    const int rows_out = min(ROUT, OUTN - r0);
    const int rows_in  = rows_out + KK - 1;

    const int base = c0 + w * WPC + lane;        // lane's first input/output col
    const int col0 = min(base,      HH - 1);     // clamped (right edge)
    const int col1 = min(base + 32, HH - 1);
    const int col2 = min(base + 64, HH - 1);

    for (int i = t; i < KK * KK; i += THREADS) s_img[i] = img[i];

    // depth-4 register prefetch ring
    float sb[DEPTH][3], vb[DEPTH][3];
#pragma unroll
    for (int d = 0; d < DEPTH; ++d) {
        const int pr = min(r0 + d, HH - 1);
        const float* sr = som + (size_t)pr * HH;
        const float* vr = var + (size_t)pr * HH;
        sb[d][0] = __ldg(sr + col0); sb[d][1] = __ldg(sr + col1); sb[d][2] = __ldg(sr + col2);
        vb[d][0] = __ldg(vr + col0); vb[d][1] = __ldg(vr + col1); vb[d][2] = __ldg(vr + col2);
    }

    __syncthreads();    // s_img ready (the ONLY barrier)

    float acc0 = 0.f, acc1 = 0.f;
    __half2* hp = hist + w * (KK * 32) + lane;   // + slot*32

    const int nloop = ((rows_in + DEPTH - 1) / DEPTH) * DEPTH;   // multiple of 4

    for (int ir = 0; ir < nloop; ir += DEPTH) {
        row_pair<0>(ir,     r0, lane, rows_in, col0, col1, col2, base,
                    som, var, s_img, hp, out, sb, vb, acc0, acc1);
        row_pair<1>(ir + 2, r0, lane, rows_in, col0, col1, col2, base,
                    som, var, s_img, hp, out, sb, vb, acc0, acc1);
    }
}

extern "C" void kernel_launch(void* const* d_in, const int* in_sizes, int n_in,
                              void* d_out, int out_size)
{
    (void)in_sizes; (void)n_in; (void)out_size;
    const float* img = (const float*)d_in[0];
    const float* som = (const float*)d_in[1];
    const float* var = (const float*)d_in[2];
    float* out = (float*)d_out;

    const size_t shmem = SMEM_BYTES;             // 69,632 B
    cudaFuncSetAttribute(som_boxdist_kernel,
                         cudaFuncAttributeMaxDynamicSharedMemorySize, (int)shmem);

    dim3 grid(NSTRIP, ROWTILES);                 // 148 blocks = 1/SM, 16 warps
    som_boxdist_kernel<<<grid, THREADS, shmem>>>(img, som, var, out);
}